// round 15
// baseline (speedup 1.0000x reference)
#include <cuda_runtime.h>
#include <cuda_fp16.h>
#include <cstdint>

#define HD    1024
#define HDW   512              // fp16 words (2 elems) per h row
#define BATCH 1024
#define SEQL  128
#define G4    4096
#define NCLS  10

#define BM 128
#define BN 256
#define BK 32                  // k elems per stage
#define LDW 20                 // row pitch in 32-bit words (16 + 4 pad)
#define KT_ITERS (HD / BK)     // 32
#define THREADS 512
#define STAGES 4
#define STAGE_W ((BM + BN) * LDW)   // words per stage = 7680

// ---- persistent device scratch (allocation-free) ----
__device__ __align__(16) __half g_WpackH[(size_t)G4 * HD]; // packed recurrent weights, fp16
__device__ float g_wxp[G4];                  // packed x-weights (IN_DIM==1), fp32
__device__ float g_bp[G4];                   // packed biases, fp32
__device__ float g_xT[(size_t)SEQL * BATCH]; // transposed input x[t][b]
__device__ __align__(16) __half g_hH[2][(size_t)BATCH * HD]; // ping-pong hidden (fp16)
__device__ float g_c[(size_t)BATCH * HD];    // cell state (fp32 — full precision)

// Packed column layout: for s = j/4, q = j%4:
//   col 16s + 2q + 0 = g_j     col 16s + 2q + 1 = i_j
//   col 16s + 8 + 2q + 0 = f_j col 16s + 8 + 2q + 1 = o_j
__global__ void pack_kernel(const float* __restrict__ wgh, const float* __restrict__ wih,
                            const float* __restrict__ wfh, const float* __restrict__ woh,
                            const float* __restrict__ wgx, const float* __restrict__ wix,
                            const float* __restrict__ wfx, const float* __restrict__ wox,
                            const float* __restrict__ bg, const float* __restrict__ bi,
                            const float* __restrict__ bf, const float* __restrict__ bo) {
    int total = G4 * HD;
    for (int idx = blockIdx.x * blockDim.x + threadIdx.x; idx < total;
         idx += gridDim.x * blockDim.x) {
        int p = idx >> 10;          // packed col
        int k = idx & (HD - 1);
        int s = p >> 4, r = p & 15;
        int q    = (r < 8) ? (r >> 1) : ((r - 8) >> 1);
        int gate = (r < 8) ? (r & 1) : (2 + (r & 1));
        int j = (s << 2) + q;
        const float* w = (gate == 0) ? wgh : (gate == 1) ? wih : (gate == 2) ? wfh : woh;
        g_WpackH[(size_t)p * HD + k] = __float2half(w[(size_t)j * HD + k]);
        if (k == 0) {
            const float* wx = (gate == 0) ? wgx : (gate == 1) ? wix : (gate == 2) ? wfx : wox;
            const float* bb = (gate == 0) ? bg  : (gate == 1) ? bi  : (gate == 2) ? bf  : bo;
            g_wxp[p] = wx[j];
            g_bp[p]  = bb[j];
        }
    }
}

__global__ void init_kernel(const float* __restrict__ x) {
    int n = BATCH * HD;
    for (int i = blockIdx.x * blockDim.x + threadIdx.x; i < n;
         i += gridDim.x * blockDim.x) {
        g_c[i] = 0.f;
        if (i < BATCH * HDW) ((uint32_t*)g_hH[0])[i] = 0u;   // zero h (fp16 pairs)
        if (i < SEQL * BATCH) {
            int t = i >> 10;            // i = t*BATCH + b
            int b = i & (BATCH - 1);
            g_xT[i] = x[b * SEQL + t];
        }
    }
}

__device__ __forceinline__ void cp16(void* s, const void* g) {
    uint32_t sa = (uint32_t)__cvta_generic_to_shared(s);
    asm volatile("cp.async.cg.shared.global [%0], [%1], 16;\n" :: "r"(sa), "l"(g) : "memory");
}

__device__ __forceinline__ void mma_f16(float& d0, float& d1, float& d2, float& d3,
                                        uint32_t a0, uint32_t a1, uint32_t a2, uint32_t a3,
                                        uint32_t b0, uint32_t b1) {
    asm volatile(
        "mma.sync.aligned.m16n8k16.row.col.f32.f16.f16.f32 "
        "{%0,%1,%2,%3}, {%4,%5,%6,%7}, {%8,%9}, {%0,%1,%2,%3};\n"
        : "+f"(d0), "+f"(d1), "+f"(d2), "+f"(d3)
        : "r"(a0), "r"(a1), "r"(a2), "r"(a3), "r"(b0), "r"(b1));
}

__device__ __forceinline__ float sigmoidf_fast(float v) {
    return 1.f / (1.f + __expf(-v));
}

// One timestep: pre = h_in @ Wpack^T (+ x_t * wxp + bias), gates, update c, write h_out.
// Grid (16, 8) = 128 CTAs. 512 threads, warps 2(m) x 8(n), warp tile 64x32.
// fp16 m16n8k16 MMA, fp32 accumulate. 4-stage cp.async pipeline.
__global__ __launch_bounds__(THREADS, 1)
void step_kernel(int t) {
    const __half* __restrict__ h_in  = g_hH[t & 1];
    __half* __restrict__       h_out = g_hH[(t + 1) & 1];

    extern __shared__ uint32_t smw[];   // fp16x2 words

    int tid = threadIdx.x;
    int lane = tid & 31, wid = tid >> 5;
    int wm = wid & 1, wn = wid >> 1;   // 2 x 8 warp grid
    int lr = lane >> 2, lc = lane & 3;

    int m0 = blockIdx.y * BM;
    int n0 = blockIdx.x * BN;

    float acc[4][4][4];
#pragma unroll
    for (int a = 0; a < 4; a++)
#pragma unroll
        for (int b = 0; b < 4; b++)
#pragma unroll
            for (int cI = 0; cI < 4; cI++) acc[a][b][cI] = 0.f;

    auto load_tiles = [&](int kt) {
        int buf = kt & (STAGES - 1);
        const __half* hA = h_in     + (size_t)m0 * HD + kt * BK;
        const __half* wB = g_WpackH + (size_t)n0 * HD + kt * BK;
        uint32_t* Ab = smw + buf * STAGE_W;
        uint32_t* Bb = Ab + BM * LDW;
        {   // A: 128 rows x 4 16B-chunks = 512 -> 1 per thread
            int row = tid >> 2, ch = tid & 3;
            cp16(Ab + row * LDW + ch * 4, hA + (size_t)row * HD + ch * 8);
        }
#pragma unroll
        for (int i = 0; i < 2; i++) {   // B: 256 rows x 4 chunks = 1024 -> 2 per thread
            int cidx = tid + i * THREADS;
            int row = cidx >> 2, ch = cidx & 3;
            cp16(Bb + row * LDW + ch * 4, wB + (size_t)row * HD + ch * 8);
        }
        asm volatile("cp.async.commit_group;\n" ::: "memory");
    };

    // prologue: fill STAGES-1 stages
#pragma unroll
    for (int s = 0; s < STAGES - 1; s++) load_tiles(s);

    for (int kt = 0; kt < KT_ITERS; kt++) {
        asm volatile("cp.async.wait_group %0;\n" :: "n"(STAGES - 2) : "memory");
        __syncthreads();

        if (kt + STAGES - 1 < KT_ITERS) load_tiles(kt + STAGES - 1);

        int buf = kt & (STAGES - 1);
        const uint32_t* Ab = smw + buf * STAGE_W + (wm * 64 + lr) * LDW;
        const uint32_t* Bb = smw + buf * STAGE_W + BM * LDW + (wn * 32 + lr) * LDW;
#pragma unroll
        for (int ks = 0; ks < 2; ks++) {     // two K=16 mma steps per BK=32
            int kw = ks * 8 + lc;            // word idx: k = 2*kw
            uint32_t af[4][4];
            uint32_t bfr[4][2];
#pragma unroll
            for (int mi = 0; mi < 4; mi++) {
                const uint32_t* ap = Ab + mi * 16 * LDW;
                af[mi][0] = ap[kw];              // (row lr,   k 2lc..2lc+1)
                af[mi][1] = ap[8 * LDW + kw];    // (row lr+8, k 2lc..)
                af[mi][2] = ap[kw + 4];          // (row lr,   k 2lc+8..)
                af[mi][3] = ap[8 * LDW + kw + 4];
            }
#pragma unroll
            for (int ni = 0; ni < 4; ni++) {
                const uint32_t* bp2 = Bb + ni * 8 * LDW;
                bfr[ni][0] = bp2[kw];            // (n lr, k 2lc..2lc+1)
                bfr[ni][1] = bp2[kw + 4];        // (n lr, k 2lc+8..)
            }
#pragma unroll
            for (int mi = 0; mi < 4; mi++)
#pragma unroll
                for (int ni = 0; ni < 4; ni++)
                    mma_f16(acc[mi][ni][0], acc[mi][ni][1], acc[mi][ni][2], acc[mi][ni][3],
                            af[mi][0], af[mi][1], af[mi][2], af[mi][3],
                            bfr[ni][0], bfr[ni][1]);
        }
    }

    // ---- epilogue: gates + LSTM state update, register-local; h packed to fp16 ----
    const float* __restrict__ xt = g_xT + (size_t)t * BATCH;
    int nbase = n0 + wn * 32;
    int jb = (nbase >> 2);     // hidden base index for this warp tile
#pragma unroll
    for (int mi = 0; mi < 4; mi++) {
        int r0 = m0 + wm * 64 + mi * 16 + lr;
        int r1 = r0 + 8;
        float x0 = xt[r0];
        float x1 = xt[r1];
#pragma unroll
        for (int p = 0; p < 2; p++) {
            int cg = nbase + p * 16 + 2 * lc;   // g col (i at +1)
            int cf = cg + 8;                    // f col (o at +1)
            int j  = jb + p * 4 + lc;           // hidden index (parity == lc parity)
            float wgv = g_wxp[cg],     wiv = g_wxp[cg + 1];
            float wfv = g_wxp[cf],     wov = g_wxp[cf + 1];
            float bgv = g_bp[cg],      biv = g_bp[cg + 1];
            float bfv = g_bp[cf],      bov = g_bp[cf + 1];
            int e = 2 * p, od = 2 * p + 1;

            // row r0
            float pg0 = acc[mi][e][0]  + x0 * wgv + bgv;
            float pi0 = acc[mi][e][1]  + x0 * wiv + biv;
            float pf0 = acc[mi][od][0] + x0 * wfv + bfv;
            float po0 = acc[mi][od][1] + x0 * wov + bov;
            float gv0 = tanhf(pg0);
            float iv0 = sigmoidf_fast(pi0);
            float fv0 = sigmoidf_fast(pf0);
            float ov0 = sigmoidf_fast(po0);
            size_t off0 = (size_t)r0 * HD + j;
            float cn0 = gv0 * iv0 + g_c[off0] * fv0;
            g_c[off0] = cn0;
            float hv0 = tanhf(cn0) * ov0;

            // row r1
            float pg1 = acc[mi][e][2]  + x1 * wgv + bgv;
            float pi1 = acc[mi][e][3]  + x1 * wiv + biv;
            float pf1 = acc[mi][od][2] + x1 * wfv + bfv;
            float po1 = acc[mi][od][3] + x1 * wov + bov;
            float gv1 = tanhf(pg1);
            float iv1 = sigmoidf_fast(pi1);
            float fv1 = sigmoidf_fast(pf1);
            float ov1 = sigmoidf_fast(po1);
            size_t off1 = (size_t)r1 * HD + j;
            float cn1 = gv1 * iv1 + g_c[off1] * fv1;
            g_c[off1] = cn1;
            float hv1 = tanhf(cn1) * ov1;

            // pack (j, j+1) fp16 pairs: odd-lc neighbor supplies j+1
            float hn0 = __shfl_down_sync(0xffffffffu, hv0, 1);
            float hn1 = __shfl_down_sync(0xffffffffu, hv1, 1);
            if ((lc & 1) == 0) {
                *(__half2*)(h_out + (size_t)r0 * HD + j) = __floats2half2_rn(hv0, hn0);
                *(__half2*)(h_out + (size_t)r1 * HD + j) = __floats2half2_rn(hv1, hn1);
            }
        }
    }
}

// logits[b,n] = h_last[b,:] . w_ph[n,:] + bias_p[n]; h_last = g_hH[0] (after 128 steps)
__global__ void logits_kernel(const float* __restrict__ wph, const float* __restrict__ bp,
                              float* __restrict__ out) {
    int b = blockIdx.x;
    int lane = threadIdx.x;   // 32 threads
    const __half2* hrow = (const __half2*)(g_hH[0] + (size_t)b * HD);
    float accv[NCLS];
#pragma unroll
    for (int n = 0; n < NCLS; n++) accv[n] = 0.f;
    for (int w = lane; w < HDW; w += 32) {
        __half2 hw = hrow[w];
        float h0 = __half2float(__low2half(hw));
        float h1 = __half2float(__high2half(hw));
#pragma unroll
        for (int n = 0; n < NCLS; n++)
            accv[n] += h0 * wph[(size_t)n * HD + 2 * w] + h1 * wph[(size_t)n * HD + 2 * w + 1];
    }
#pragma unroll
    for (int n = 0; n < NCLS; n++)
#pragma unroll
        for (int off = 16; off; off >>= 1)
            accv[n] += __shfl_xor_sync(0xffffffffu, accv[n], off);
    if (lane < NCLS) out[b * NCLS + lane] = accv[lane] + bp[lane];
}

extern "C" void kernel_launch(void* const* d_in, const int* in_sizes, int n_in,
                              void* d_out, int out_size) {
    const float* x   = (const float*)d_in[0];
    const float* wgx = (const float*)d_in[1];
    const float* wgh = (const float*)d_in[2];
    const float* wix = (const float*)d_in[3];
    const float* wih = (const float*)d_in[4];
    const float* wfx = (const float*)d_in[5];
    const float* wfh = (const float*)d_in[6];
    const float* wox = (const float*)d_in[7];
    const float* woh = (const float*)d_in[8];
    const float* wph = (const float*)d_in[9];
    const float* bg  = (const float*)d_in[10];
    const float* bi  = (const float*)d_in[11];
    const float* bf  = (const float*)d_in[12];
    const float* bo  = (const float*)d_in[13];
    const float* bp  = (const float*)d_in[14];
    float* out = (float*)d_out;

    const int SMEM_BYTES = STAGES * STAGE_W * (int)sizeof(uint32_t);  // 122880
    cudaFuncSetAttribute(step_kernel, cudaFuncAttributeMaxDynamicSharedMemorySize, SMEM_BYTES);

    pack_kernel<<<2048, 256>>>(wgh, wih, wfh, woh, wgx, wix, wfx, wox, bg, bi, bf, bo);
    init_kernel<<<2048, 256>>>(x);

    dim3 grid(G4 / BN, BATCH / BM);   // (16, 8) = 128 CTAs
    for (int t = 0; t < SEQL; t++)
        step_kernel<<<grid, THREADS, SMEM_BYTES>>>(t);

    logits_kernel<<<BATCH, 32>>>(wph, bp, out);
}

// round 16
// speedup vs baseline: 2.0174x; 2.0174x over previous
#include <cuda_runtime.h>
#include <cuda_fp16.h>
#include <cstdint>

#define HD    1024
#define HDW   512              // fp16 pairs per h row
#define BATCH 1024
#define SEQL  128
#define G4    4096
#define NCLS  10

#define BM 128
#define BN 256
#define BK 128                 // k elems per stage (256B/row)
#define LDW 68                 // row pitch in 32-bit words (64 + 4 pad)
#define KT_ITERS (HD / BK)     // 8
#define THREADS 512
#define STAGES 2
#define STAGE_W ((BM + BN) * LDW)   // words per stage = 26112 (104448 B)

// ---- persistent device scratch (allocation-free) ----
__device__ __align__(16) __half g_WpackH[(size_t)G4 * HD]; // packed recurrent weights, fp16
__device__ float g_wxp[G4];                  // packed x-weights (IN_DIM==1), fp32
__device__ float g_bp[G4];                   // packed biases, fp32
__device__ float g_xT[(size_t)SEQL * BATCH]; // transposed input x[t][b]
__device__ __align__(16) __half g_hH[2][(size_t)BATCH * HD]; // ping-pong hidden (fp16)
__device__ float g_c[(size_t)BATCH * HD];    // cell state (fp32 — full precision)

// Packed column layout: for s = j/4, q = j%4:
//   col 16s + 2q + 0 = g_j     col 16s + 2q + 1 = i_j
//   col 16s + 8 + 2q + 0 = f_j col 16s + 8 + 2q + 1 = o_j
__global__ void pack_kernel(const float* __restrict__ wgh, const float* __restrict__ wih,
                            const float* __restrict__ wfh, const float* __restrict__ woh,
                            const float* __restrict__ wgx, const float* __restrict__ wix,
                            const float* __restrict__ wfx, const float* __restrict__ wox,
                            const float* __restrict__ bg, const float* __restrict__ bi,
                            const float* __restrict__ bf, const float* __restrict__ bo) {
    int total = G4 * HD;
    for (int idx = blockIdx.x * blockDim.x + threadIdx.x; idx < total;
         idx += gridDim.x * blockDim.x) {
        int p = idx >> 10;          // packed col
        int k = idx & (HD - 1);
        int s = p >> 4, r = p & 15;
        int q    = (r < 8) ? (r >> 1) : ((r - 8) >> 1);
        int gate = (r < 8) ? (r & 1) : (2 + (r & 1));
        int j = (s << 2) + q;
        const float* w = (gate == 0) ? wgh : (gate == 1) ? wih : (gate == 2) ? wfh : woh;
        g_WpackH[(size_t)p * HD + k] = __float2half(w[(size_t)j * HD + k]);
        if (k == 0) {
            const float* wx = (gate == 0) ? wgx : (gate == 1) ? wix : (gate == 2) ? wfx : wox;
            const float* bb = (gate == 0) ? bg  : (gate == 1) ? bi  : (gate == 2) ? bf  : bo;
            g_wxp[p] = wx[j];
            g_bp[p]  = bb[j];
        }
    }
}

__global__ void init_kernel(const float* __restrict__ x) {
    int n = BATCH * HD;
    for (int i = blockIdx.x * blockDim.x + threadIdx.x; i < n;
         i += gridDim.x * blockDim.x) {
        g_c[i] = 0.f;
        if (i < BATCH * HDW) ((uint32_t*)g_hH[0])[i] = 0u;   // zero h (fp16 pairs)
        if (i < SEQL * BATCH) {
            int t = i >> 10;            // i = t*BATCH + b
            int b = i & (BATCH - 1);
            g_xT[i] = x[b * SEQL + t];
        }
    }
}

__device__ __forceinline__ void cp16(void* s, const void* g) {
    uint32_t sa = (uint32_t)__cvta_generic_to_shared(s);
    asm volatile("cp.async.cg.shared.global [%0], [%1], 16;\n" :: "r"(sa), "l"(g) : "memory");
}

__device__ __forceinline__ void mma_f16(float& d0, float& d1, float& d2, float& d3,
                                        uint32_t a0, uint32_t a1, uint32_t a2, uint32_t a3,
                                        uint32_t b0, uint32_t b1) {
    asm volatile(
        "mma.sync.aligned.m16n8k16.row.col.f32.f16.f16.f32 "
        "{%0,%1,%2,%3}, {%4,%5,%6,%7}, {%8,%9}, {%0,%1,%2,%3};\n"
        : "+f"(d0), "+f"(d1), "+f"(d2), "+f"(d3)
        : "r"(a0), "r"(a1), "r"(a2), "r"(a3), "r"(b0), "r"(b1));
}

__device__ __forceinline__ float sigmoidf_fast(float v) {
    return 1.f / (1.f + __expf(-v));
}

// One timestep: pre = h_in @ Wpack^T (+ x_t * wxp + bias), gates, update c, write h_out.
// Grid (16, 8) = 128 CTAs. 512 threads, warps 2(m) x 8(n), warp tile 64x32.
// fp16 m16n8k16 MMA, fp32 accumulate. BK=128: only 8 sync quanta per step.
__global__ __launch_bounds__(THREADS, 1)
void step_kernel(int t) {
    const __half* __restrict__ h_in  = g_hH[t & 1];
    __half* __restrict__       h_out = g_hH[(t + 1) & 1];

    extern __shared__ uint32_t smw[];   // fp16x2 words

    int tid = threadIdx.x;
    int lane = tid & 31, wid = tid >> 5;
    int wm = wid & 1, wn = wid >> 1;   // 2 x 8 warp grid
    int lr = lane >> 2, lc = lane & 3;

    int m0 = blockIdx.y * BM;
    int n0 = blockIdx.x * BN;

    float acc[4][4][4];
#pragma unroll
    for (int a = 0; a < 4; a++)
#pragma unroll
        for (int b = 0; b < 4; b++)
#pragma unroll
            for (int cI = 0; cI < 4; cI++) acc[a][b][cI] = 0.f;

    auto load_tiles = [&](int kt) {
        int buf = kt & 1;
        const __half* hA = h_in     + (size_t)m0 * HD + kt * BK;
        const __half* wB = g_WpackH + (size_t)n0 * HD + kt * BK;
        uint32_t* Ab = smw + buf * STAGE_W;
        uint32_t* Bb = Ab + BM * LDW;
#pragma unroll
        for (int i = 0; i < 4; i++) {   // A: 128 rows x 16 chunks = 2048 -> 4/thread
            int cidx = tid + i * THREADS;
            int row = cidx >> 4, ch = cidx & 15;
            cp16(Ab + row * LDW + ch * 4, hA + (size_t)row * HD + ch * 8);
        }
#pragma unroll
        for (int i = 0; i < 8; i++) {   // B: 256 rows x 16 chunks = 4096 -> 8/thread
            int cidx = tid + i * THREADS;
            int row = cidx >> 4, ch = cidx & 15;
            cp16(Bb + row * LDW + ch * 4, wB + (size_t)row * HD + ch * 8);
        }
        asm volatile("cp.async.commit_group;\n" ::: "memory");
    };

    // prologue: fill both stages
    load_tiles(0);
    load_tiles(1);

    for (int kt = 0; kt < KT_ITERS; kt++) {
        // stage kt arrived when <=1 newer group pending (or 0 on last iter)
        if (kt < KT_ITERS - 1)
            asm volatile("cp.async.wait_group 1;\n" ::: "memory");
        else
            asm volatile("cp.async.wait_group 0;\n" ::: "memory");
        __syncthreads();

        const uint32_t* Ab = smw + (kt & 1) * STAGE_W + (wm * 64 + lr) * LDW;
        const uint32_t* Bb = smw + (kt & 1) * STAGE_W + BM * LDW + (wn * 32 + lr) * LDW;
#pragma unroll
        for (int ks = 0; ks < 8; ks++) {     // eight K=16 mma steps per BK=128
            int kw = ks * 8 + lc;            // word idx: k = 2*kw
            uint32_t af[4][4];
            uint32_t bfr[4][2];
#pragma unroll
            for (int mi = 0; mi < 4; mi++) {
                const uint32_t* ap = Ab + mi * 16 * LDW;
                af[mi][0] = ap[kw];
                af[mi][1] = ap[8 * LDW + kw];
                af[mi][2] = ap[kw + 4];
                af[mi][3] = ap[8 * LDW + kw + 4];
            }
#pragma unroll
            for (int ni = 0; ni < 4; ni++) {
                const uint32_t* bp2 = Bb + ni * 8 * LDW;
                bfr[ni][0] = bp2[kw];
                bfr[ni][1] = bp2[kw + 4];
            }
#pragma unroll
            for (int mi = 0; mi < 4; mi++)
#pragma unroll
                for (int ni = 0; ni < 4; ni++)
                    mma_f16(acc[mi][ni][0], acc[mi][ni][1], acc[mi][ni][2], acc[mi][ni][3],
                            af[mi][0], af[mi][1], af[mi][2], af[mi][3],
                            bfr[ni][0], bfr[ni][1]);
        }

        // reuse of this buffer by load(kt+2): all warps must be done reading it
        if (kt + 2 < KT_ITERS) {
            __syncthreads();
            load_tiles(kt + 2);
        }
    }

    // ---- epilogue: gates + LSTM state update, register-local; h packed to fp16 ----
    const float* __restrict__ xt = g_xT + (size_t)t * BATCH;
    int nbase = n0 + wn * 32;
    int jb = (nbase >> 2);     // hidden base index for this warp tile
#pragma unroll
    for (int mi = 0; mi < 4; mi++) {
        int r0 = m0 + wm * 64 + mi * 16 + lr;
        int r1 = r0 + 8;
        float x0 = xt[r0];
        float x1 = xt[r1];
#pragma unroll
        for (int p = 0; p < 2; p++) {
            int cg = nbase + p * 16 + 2 * lc;   // g col (i at +1)
            int cf = cg + 8;                    // f col (o at +1)
            int j  = jb + p * 4 + lc;           // hidden index
            float wgv = g_wxp[cg],     wiv = g_wxp[cg + 1];
            float wfv = g_wxp[cf],     wov = g_wxp[cf + 1];
            float bgv = g_bp[cg],      biv = g_bp[cg + 1];
            float bfv = g_bp[cf],      bov = g_bp[cf + 1];
            int e = 2 * p, od = 2 * p + 1;

            // row r0
            float pg0 = acc[mi][e][0]  + x0 * wgv + bgv;
            float pi0 = acc[mi][e][1]  + x0 * wiv + biv;
            float pf0 = acc[mi][od][0] + x0 * wfv + bfv;
            float po0 = acc[mi][od][1] + x0 * wov + bov;
            float gv0 = tanhf(pg0);
            float iv0 = sigmoidf_fast(pi0);
            float fv0 = sigmoidf_fast(pf0);
            float ov0 = sigmoidf_fast(po0);
            size_t off0 = (size_t)r0 * HD + j;
            float cn0 = gv0 * iv0 + g_c[off0] * fv0;
            g_c[off0] = cn0;
            float hv0 = tanhf(cn0) * ov0;

            // row r1
            float pg1 = acc[mi][e][2]  + x1 * wgv + bgv;
            float pi1 = acc[mi][e][3]  + x1 * wiv + biv;
            float pf1 = acc[mi][od][2] + x1 * wfv + bfv;
            float po1 = acc[mi][od][3] + x1 * wov + bov;
            float gv1 = tanhf(pg1);
            float iv1 = sigmoidf_fast(pi1);
            float fv1 = sigmoidf_fast(pf1);
            float ov1 = sigmoidf_fast(po1);
            size_t off1 = (size_t)r1 * HD + j;
            float cn1 = gv1 * iv1 + g_c[off1] * fv1;
            g_c[off1] = cn1;
            float hv1 = tanhf(cn1) * ov1;

            // pack (j, j+1) fp16 pairs: odd-lc neighbor supplies j+1
            float hn0 = __shfl_down_sync(0xffffffffu, hv0, 1);
            float hn1 = __shfl_down_sync(0xffffffffu, hv1, 1);
            if ((lc & 1) == 0) {
                *(__half2*)(h_out + (size_t)r0 * HD + j) = __floats2half2_rn(hv0, hn0);
                *(__half2*)(h_out + (size_t)r1 * HD + j) = __floats2half2_rn(hv1, hn1);
            }
        }
    }
}

// logits[b,n] = h_last[b,:] . w_ph[n,:] + bias_p[n]; h_last = g_hH[0] (after 128 steps)
__global__ void logits_kernel(const float* __restrict__ wph, const float* __restrict__ bp,
                              float* __restrict__ out) {
    int b = blockIdx.x;
    int lane = threadIdx.x;   // 32 threads
    const __half2* hrow = (const __half2*)(g_hH[0] + (size_t)b * HD);
    float accv[NCLS];
#pragma unroll
    for (int n = 0; n < NCLS; n++) accv[n] = 0.f;
    for (int w = lane; w < HDW; w += 32) {
        __half2 hw = hrow[w];
        float h0 = __half2float(__low2half(hw));
        float h1 = __half2float(__high2half(hw));
#pragma unroll
        for (int n = 0; n < NCLS; n++)
            accv[n] += h0 * wph[(size_t)n * HD + 2 * w] + h1 * wph[(size_t)n * HD + 2 * w + 1];
    }
#pragma unroll
    for (int n = 0; n < NCLS; n++)
#pragma unroll
        for (int off = 16; off; off >>= 1)
            accv[n] += __shfl_xor_sync(0xffffffffu, accv[n], off);
    if (lane < NCLS) out[b * NCLS + lane] = accv[lane] + bp[lane];
}

extern "C" void kernel_launch(void* const* d_in, const int* in_sizes, int n_in,
                              void* d_out, int out_size) {
    const float* x   = (const float*)d_in[0];
    const float* wgx = (const float*)d_in[1];
    const float* wgh = (const float*)d_in[2];
    const float* wix = (const float*)d_in[3];
    const float* wih = (const float*)d_in[4];
    const float* wfx = (const float*)d_in[5];
    const float* wfh = (const float*)d_in[6];
    const float* wox = (const float*)d_in[7];
    const float* woh = (const float*)d_in[8];
    const float* wph = (const float*)d_in[9];
    const float* bg  = (const float*)d_in[10];
    const float* bi  = (const float*)d_in[11];
    const float* bf  = (const float*)d_in[12];
    const float* bo  = (const float*)d_in[13];
    const float* bp  = (const float*)d_in[14];
    float* out = (float*)d_out;

    const int SMEM_BYTES = STAGES * STAGE_W * (int)sizeof(uint32_t);  // 208896
    cudaFuncSetAttribute(step_kernel, cudaFuncAttributeMaxDynamicSharedMemorySize, SMEM_BYTES);

    pack_kernel<<<2048, 256>>>(wgh, wih, wfh, woh, wgx, wix, wfx, wox, bg, bi, bf, bo);
    init_kernel<<<2048, 256>>>(x);

    dim3 grid(G4 / BN, BATCH / BM);   // (16, 8) = 128 CTAs
    for (int t = 0; t < SEQL; t++)
        step_kernel<<<grid, THREADS, SMEM_BYTES>>>(t);

    logits_kernel<<<BATCH, 32>>>(wph, bp, out);
}